// round 4
// baseline (speedup 1.0000x reference)
#include <cuda_runtime.h>

#define BATCH 64
#define TDIM  2048
#define QDIM  512
#define KDIM  512
#define QSPLIT 4
#define QCHUNK (QDIM / QSPLIT)   // 128

// Scratch (no allocations allowed in kernel_launch)
__device__ float    g_part[QSPLIT][BATCH * KDIM];  // partial mids per q-chunk
__device__ float    g_sums[BATCH];
__device__ unsigned g_count[BATCH];

// ---------------------------------------------------------------------------
// Kernel 1: partial mids. g_part[qs][b,k] = sum_{q in chunk} W[k,q]*query[b,q]
// grid = 2048: qs = x&3, kt = (x>>2)&31 (32 tiles of 16 k), bt = x>>7 (16
// tiles of 4 batches). 256 threads = 8 warps; each warp owns ONE k-pair:
// a single L2 W load -> FMA -> one shfl-reduce chain. Max parallelism,
// minimal serial depth. Block 0 also zeroes g_sums / g_count.
// ---------------------------------------------------------------------------
__global__ void __launch_bounds__(256)
mids_kernel(const float* __restrict__ query,
            const float* __restrict__ W)
{
    const int qs = blockIdx.x & 3;
    const int kt = (blockIdx.x >> 2) & 31;   // 0..31 (16 k each)
    const int bt = blockIdx.x >> 7;          // 0..15 (4 b each)

    if (blockIdx.x == 0 && threadIdx.x < BATCH) {
        g_sums[threadIdx.x]  = 0.0f;
        g_count[threadIdx.x] = 0u;
    }

    __shared__ float q_s[4][QCHUNK];
    for (int i = threadIdx.x; i < 4 * QCHUNK; i += blockDim.x) {
        int bb = i >> 7;
        int q  = i & (QCHUNK - 1);
        q_s[bb][q] = query[(size_t)(bt * 4 + bb) * QDIM + qs * QCHUNK + q];
    }
    __syncthreads();

    const int warp = threadIdx.x >> 5;
    const int lane = threadIdx.x & 31;

    float4 qv[4];
#pragma unroll
    for (int bb = 0; bb < 4; bb++)
        qv[bb] = reinterpret_cast<const float4*>(q_s[bb])[lane];

    const int k0 = kt * 16 + warp * 2;
    const int k1 = k0 + 1;
    const float4 wa = reinterpret_cast<const float4*>(
        W + (size_t)k0 * QDIM + qs * QCHUNK)[lane];
    const float4 wb = reinterpret_cast<const float4*>(
        W + (size_t)k1 * QDIM + qs * QCHUNK)[lane];

    float a[2][4];
#pragma unroll
    for (int bb = 0; bb < 4; bb++) {
        const float4 v = qv[bb];
        a[0][bb] = wa.x * v.x + wa.y * v.y + wa.z * v.z + wa.w * v.w;
        a[1][bb] = wb.x * v.x + wb.y * v.y + wb.z * v.z + wb.w * v.w;
    }
#pragma unroll
    for (int o = 16; o; o >>= 1) {
#pragma unroll
        for (int bb = 0; bb < 4; bb++) {
            a[0][bb] += __shfl_xor_sync(0xffffffffu, a[0][bb], o);
            a[1][bb] += __shfl_xor_sync(0xffffffffu, a[1][bb], o);
        }
    }
    if (lane == 0) {
#pragma unroll
        for (int bb = 0; bb < 4; bb++) {
            const int b = bt * 4 + bb;
            g_part[qs][(size_t)b * KDIM + k0] = a[0][bb];
            g_part[qs][(size_t)b * KDIM + k1] = a[1][bb];
        }
    }
}

// ---------------------------------------------------------------------------
// Kernel 2: e[b,t] = exp(tanh(key[b,t,:] . mids[b,:] + bias)); accumulate
// per-batch sums; the LAST block of each batch normalizes that batch in
// place (fused softmax denominator -> no third kernel).
// tanh in (-1,1) -> exp bounded in (1/e, e) -> no max-subtraction needed.
// grid = 64*64 = 4096 blocks (fine granularity: ~7 waves, tiny tail),
// 256 threads = 8 warps, 4 rows per warp (16 streaming LDG.128 in flight).
// mids staged via smem once per block, then held in registers per warp.
// ---------------------------------------------------------------------------
__global__ void __launch_bounds__(256)
scores_kernel(const float* __restrict__ key,
              const float* __restrict__ bias,
              float* __restrict__ out)
{
    const int b     = blockIdx.x >> 6;   // 0..63
    const int chunk = blockIdx.x & 63;   // 0..63 (32 rows each)

    __shared__ float ms[KDIM];
    __shared__ float blockSum;
    __shared__ int   isLast;
    __shared__ float invTotal;
    if (threadIdx.x == 0) { blockSum = 0.0f; isLast = 0; }

    // mids = sum of 4 q-chunk partials, staged in smem (one L2 read/block)
    {
        const float4* p0 = reinterpret_cast<const float4*>(g_part[0] + (size_t)b * KDIM);
        const float4* p1 = reinterpret_cast<const float4*>(g_part[1] + (size_t)b * KDIM);
        const float4* p2 = reinterpret_cast<const float4*>(g_part[2] + (size_t)b * KDIM);
        const float4* p3 = reinterpret_cast<const float4*>(g_part[3] + (size_t)b * KDIM);
        if (threadIdx.x < KDIM / 4) {
            const int i = threadIdx.x;
            float4 x0 = p0[i], x1 = p1[i], x2 = p2[i], x3 = p3[i];
            float4 s;
            s.x = (x0.x + x1.x) + (x2.x + x3.x);
            s.y = (x0.y + x1.y) + (x2.y + x3.y);
            s.z = (x0.z + x1.z) + (x2.z + x3.z);
            s.w = (x0.w + x1.w) + (x2.w + x3.w);
            reinterpret_cast<float4*>(ms)[i] = s;
        }
    }
    __syncthreads();

    const int warp = threadIdx.x >> 5;
    const int lane = threadIdx.x & 31;

    float4 m[4];
#pragma unroll
    for (int j = 0; j < 4; j++)
        m[j] = reinterpret_cast<const float4*>(ms)[lane + 32 * j];

    const float bv = bias[0];
    const int ta = chunk * 32 + warp * 4;

    const float4* kb = reinterpret_cast<const float4*>(
        key + ((size_t)b * TDIM + ta) * KDIM);

    float a0 = 0.f, a1 = 0.f, a2 = 0.f, a3 = 0.f;
#pragma unroll
    for (int j = 0; j < 4; j++) {
        const int idx = lane + 32 * j;
        const float4 mv = m[j];
        float4 v0 = __ldcs(kb + idx + 0 * 128);
        float4 v1 = __ldcs(kb + idx + 1 * 128);
        float4 v2 = __ldcs(kb + idx + 2 * 128);
        float4 v3 = __ldcs(kb + idx + 3 * 128);
        a0 += v0.x * mv.x + v0.y * mv.y + v0.z * mv.z + v0.w * mv.w;
        a1 += v1.x * mv.x + v1.y * mv.y + v1.z * mv.z + v1.w * mv.w;
        a2 += v2.x * mv.x + v2.y * mv.y + v2.z * mv.z + v2.w * mv.w;
        a3 += v3.x * mv.x + v3.y * mv.y + v3.z * mv.z + v3.w * mv.w;
    }
#pragma unroll
    for (int o = 16; o; o >>= 1) {
        a0 += __shfl_xor_sync(0xffffffffu, a0, o);
        a1 += __shfl_xor_sync(0xffffffffu, a1, o);
        a2 += __shfl_xor_sync(0xffffffffu, a2, o);
        a3 += __shfl_xor_sync(0xffffffffu, a3, o);
    }

    if (lane == 0) {
        float4 e;
        e.x = __expf(tanhf(a0 + bv));
        e.y = __expf(tanhf(a1 + bv));
        e.z = __expf(tanhf(a2 + bv));
        e.w = __expf(tanhf(a3 + bv));
        *reinterpret_cast<float4*>(out + (size_t)b * TDIM + ta) = e;
        __threadfence();  // make this warp's output visible device-wide
        atomicAdd(&blockSum, (e.x + e.y) + (e.z + e.w));
    }
    __syncthreads();

    if (threadIdx.x == 0) {
        atomicAdd(&g_sums[b], blockSum);
        __threadfence();
        unsigned old = atomicAdd(&g_count[b], 1u);
        if (old == 63u) {  // last block for this batch: all sums + outputs done
            isLast = 1;
            __threadfence();
            invTotal = 1.0f / atomicAdd(&g_sums[b], 0.0f);
        }
    }
    __syncthreads();

    if (isLast) {
        const float inv = invTotal;
        float4* o4 = reinterpret_cast<float4*>(out + (size_t)b * TDIM);
#pragma unroll
        for (int r = 0; r < 2; r++) {
            const int i = threadIdx.x + r * 256;  // 512 float4 per batch
            float4 v = __ldcg(&o4[i]);
            v.x *= inv; v.y *= inv; v.z *= inv; v.w *= inv;
            o4[i] = v;
        }
    }
}

// ---------------------------------------------------------------------------
// Inputs (metadata order): query [64,512], key [64,2048,512], W [512,512],
// bias [1]. Output: [64,2048] float32.
// ---------------------------------------------------------------------------
extern "C" void kernel_launch(void* const* d_in, const int* in_sizes, int n_in,
                              void* d_out, int out_size)
{
    const float* query = (const float*)d_in[0];
    const float* key   = (const float*)d_in[1];
    const float* W     = (const float*)d_in[2];
    const float* bias  = (const float*)d_in[3];
    float* out = (float*)d_out;

    mids_kernel<<<2048, 256>>>(query, W);
    scores_kernel<<<BATCH * 64, 256>>>(key, bias, out);
}